// round 4
// baseline (speedup 1.0000x reference)
#include <cuda_runtime.h>
#include <cuda_bf16.h>
#include <cstdint>

// ---------------------------------------------------------------------------
// Problem constants
// ---------------------------------------------------------------------------
namespace cfg {
constexpr int Dm   = 1024;
constexpr int NH   = 16;
constexpr int DK   = 64;
constexpr int CH   = 64;
constexpr int B    = 4;
constexpr int L    = 4096;
constexpr int NC   = L / CH;   // 64
constexpr int T    = B * L;    // 16384
constexpr int QC   = 3 * Dm;   // 3072
}

// ---------------------------------------------------------------------------
// Static device scratch
// ---------------------------------------------------------------------------
__device__ float          g_qkv[(size_t)cfg::T * cfg::QC];
__device__ float          g_state[(size_t)cfg::B * cfg::NH * cfg::NC * cfg::DK * cfg::DK];
__device__ float          g_y[(size_t)cfg::T * cfg::Dm];
__device__ __nv_bfloat16  g_ahi[(size_t)cfg::T * cfg::Dm];
__device__ __nv_bfloat16  g_alo[(size_t)cfg::T * cfg::Dm];
__device__ __nv_bfloat16  g_wqh[(size_t)cfg::QC * cfg::Dm];
__device__ __nv_bfloat16  g_wql[(size_t)cfg::QC * cfg::Dm];
__device__ __nv_bfloat16  g_woh[(size_t)cfg::Dm * cfg::Dm];
__device__ __nv_bfloat16  g_wol[(size_t)cfg::Dm * cfg::Dm];

// ---------------------------------------------------------------------------
// PTX helpers
// ---------------------------------------------------------------------------
__device__ __forceinline__ uint32_t smem_u32(const void* p) {
    uint32_t a;
    asm("{ .reg .u64 t; cvta.to.shared.u64 t, %1; cvt.u32.u64 %0, t; }"
        : "=r"(a) : "l"(p));
    return a;
}
#define CP16(dst, src) \
    asm volatile("cp.async.cg.shared.global [%0], [%1], 16;" :: "r"(dst), "l"(src))
#define CP_COMMIT() asm volatile("cp.async.commit_group;" ::: "memory")
#define CP_WAIT(n)  asm volatile("cp.async.wait_group %0;" :: "n"(n) : "memory")

__device__ __forceinline__ void ldsm4(uint32_t* r, uint32_t addr) {
    asm volatile("ldmatrix.sync.aligned.m8n8.x4.shared.b16 {%0,%1,%2,%3}, [%4];"
                 : "=r"(r[0]), "=r"(r[1]), "=r"(r[2]), "=r"(r[3]) : "r"(addr));
}
__device__ __forceinline__ void mma16816(float* c, const uint32_t* a, const uint32_t* b) {
    asm volatile(
        "mma.sync.aligned.m16n8k16.row.col.f32.bf16.bf16.f32 "
        "{%0,%1,%2,%3}, {%4,%5,%6,%7}, {%8,%9}, {%0,%1,%2,%3};"
        : "+f"(c[0]), "+f"(c[1]), "+f"(c[2]), "+f"(c[3])
        : "r"(a[0]), "r"(a[1]), "r"(a[2]), "r"(a[3]), "r"(b[0]), "r"(b[1]));
}

// ---------------------------------------------------------------------------
// bf16 3x-split GEMM via HMMA:
//   C[M,N](fp32) = Ah@Bh^T + Ah@Bl^T + Al@Bh^T
//   A*: [M,K] bf16 row-major. B*: [N,K] bf16 row-major (pre-transposed W).
//   CTA tile 128x256, warp tile 64x64 (2x4 warps), K-chunk = 64 halves.
//   2-stage cp.async (96 KiB/stage). Rows 128B, swizzle c ^= (row & 7).
// ---------------------------------------------------------------------------
namespace gm {
constexpr int A_TILE_B = 128 * 128;        // 16 KiB (128 rows x 128B)
constexpr int B_TILE_B = 256 * 128;        // 32 KiB (256 rows x 128B)
constexpr int STAGE_B  = 2 * A_TILE_B + 2 * B_TILE_B;  // 96 KiB
constexpr int SMEM_SZ  = 2 * STAGE_B;       // 192 KiB
}

__global__ __launch_bounds__(256, 1) void gemm_mma_kernel(
    const __nv_bfloat16* __restrict__ Ah, const __nv_bfloat16* __restrict__ Al,
    const __nv_bfloat16* __restrict__ Bh, const __nv_bfloat16* __restrict__ Bl,
    float* __restrict__ C, int N, int K)
{
    extern __shared__ char smem[];
    const uint32_t sb = smem_u32(smem);
    const int tid = threadIdx.x, wid = tid >> 5, lane = tid & 31;
    const int tn = blockIdx.x, tm = blockIdx.y;
    const int wm = wid >> 2;   // 0..1 : 64-row slab
    const int wn = wid & 3;    // 0..3 : 64-col slab

    const __nv_bfloat16* aA[2] = { Ah + (size_t)tm * 128 * K, Al + (size_t)tm * 128 * K };
    const __nv_bfloat16* bB[2] = { Bh + (size_t)tn * 256 * K, Bl + (size_t)tn * 256 * K };

    // A staging: 2 threads/row, 4 chunks each.  B staging: 1 thread/row, 8 chunks.
    const int arow = tid >> 1, ac0 = (tid & 1) * 4;

    auto load_stage = [&](int chunk, int stage) {
        const uint32_t st = sb + stage * gm::STAGE_B;
#pragma unroll
        for (int t2 = 0; t2 < 2; ++t2) {
            const __nv_bfloat16* p = aA[t2] + (size_t)arow * K + chunk * 64;
            const uint32_t dst = st + t2 * gm::A_TILE_B + arow * 128;
#pragma unroll
            for (int cc = 0; cc < 4; ++cc) {
                const int c = ac0 + cc;
                CP16(dst + ((c ^ (arow & 7)) * 16), p + c * 8);
            }
        }
#pragma unroll
        for (int t2 = 0; t2 < 2; ++t2) {
            const __nv_bfloat16* p = bB[t2] + (size_t)tid * K + chunk * 64;
            const uint32_t dst = st + 2 * gm::A_TILE_B + t2 * gm::B_TILE_B + tid * 128;
#pragma unroll
            for (int c = 0; c < 8; ++c)
                CP16(dst + ((c ^ (tid & 7)) * 16), p + c * 8);
        }
    };

    float acc[4][8][4];
#pragma unroll
    for (int t = 0; t < 4; ++t)
#pragma unroll
        for (int j = 0; j < 8; ++j)
#pragma unroll
            for (int r = 0; r < 4; ++r) acc[t][j][r] = 0.f;

    const int NK = K >> 6;
    load_stage(0, 0); CP_COMMIT();
    load_stage(1, 1); CP_COMMIT();

    for (int i = 0; i < NK; ++i) {
        CP_WAIT(1);                 // group i complete (uniform commit per iter)
        __syncthreads();

        const uint32_t st  = sb + (i & 1) * gm::STAGE_B;
        const uint32_t ahB = st;
        const uint32_t alB = st + gm::A_TILE_B;
        const uint32_t bhB = st + 2 * gm::A_TILE_B;
        const uint32_t blB = st + 2 * gm::A_TILE_B + gm::B_TILE_B;

#pragma unroll
        for (int s = 0; s < 4; ++s) {          // k16 steps within 64-half chunk
            uint32_t ah[4][4], al[4][4];
#pragma unroll
            for (int t = 0; t < 4; ++t) {
                const int row = wm * 64 + t * 16 + (lane & 15);
                const int c   = s * 2 + (lane >> 4);
                const uint32_t off = row * 128 + ((c ^ (row & 7)) * 16);
                ldsm4(ah[t], ahB + off);
                ldsm4(al[t], alB + off);
            }
            uint32_t bh[8][2], bl[8][2];
#pragma unroll
            for (int p = 0; p < 4; ++p) {      // 4 ldsm cover 8 n8-tiles
                const int row = wn * 64 + p * 16 + ((lane & 16) >> 1) + (lane & 7);
                const int c   = s * 2 + ((lane >> 3) & 1);
                const uint32_t off = row * 128 + ((c ^ (row & 7)) * 16);
                uint32_t r[4];
                ldsm4(r, bhB + off);
                bh[2 * p][0] = r[0]; bh[2 * p][1] = r[1];
                bh[2 * p + 1][0] = r[2]; bh[2 * p + 1][1] = r[3];
                ldsm4(r, blB + off);
                bl[2 * p][0] = r[0]; bl[2 * p][1] = r[1];
                bl[2 * p + 1][0] = r[2]; bl[2 * p + 1][1] = r[3];
            }
#pragma unroll
            for (int t = 0; t < 4; ++t)
#pragma unroll
                for (int j = 0; j < 8; ++j) {
                    mma16816(acc[t][j], ah[t], bh[j]);
                    mma16816(acc[t][j], ah[t], bl[j]);
                    mma16816(acc[t][j], al[t], bh[j]);
                }
        }
        __syncthreads();            // all reads done before overwriting buffer
        if (i + 2 < NK) load_stage(i + 2, (i & 1));
        CP_COMMIT();                // uniform group count (may be empty)
    }

    // epilogue
    const int qr = lane >> 2, qc = (lane & 3) * 2;
#pragma unroll
    for (int t = 0; t < 4; ++t) {
        const int r0 = tm * 128 + wm * 64 + t * 16 + qr;
#pragma unroll
        for (int j = 0; j < 8; ++j) {
            const int col = tn * 256 + wn * 64 + j * 8 + qc;
            *(float2*)(C + (size_t)r0 * N + col)       = make_float2(acc[t][j][0], acc[t][j][1]);
            *(float2*)(C + (size_t)(r0 + 8) * N + col) = make_float2(acc[t][j][2], acc[t][j][3]);
        }
    }
}

// ---------------------------------------------------------------------------
// fp32 -> bf16 hi/lo split
// ---------------------------------------------------------------------------
__global__ __launch_bounds__(256) void split_kernel(
    const float* __restrict__ in, __nv_bfloat16* __restrict__ hi,
    __nv_bfloat16* __restrict__ lo, int n4)
{
    const int i = blockIdx.x * 256 + threadIdx.x;
    if (i >= n4) return;
    const float4 v = *(const float4*)(in + (size_t)i * 4);
    float xs[4] = {v.x, v.y, v.z, v.w};
    __nv_bfloat16 h[4], l[4];
#pragma unroll
    for (int j = 0; j < 4; ++j) {
        h[j] = __float2bfloat16_rn(xs[j]);
        l[j] = __float2bfloat16_rn(xs[j] - __bfloat162float(h[j]));
    }
    *(__nv_bfloat162*)(hi + (size_t)i * 4)     = __nv_bfloat162(h[0], h[1]);
    *(__nv_bfloat162*)(hi + (size_t)i * 4 + 2) = __nv_bfloat162(h[2], h[3]);
    *(__nv_bfloat162*)(lo + (size_t)i * 4)     = __nv_bfloat162(l[0], l[1]);
    *(__nv_bfloat162*)(lo + (size_t)i * 4 + 2) = __nv_bfloat162(l[2], l[3]);
}

// ---------------------------------------------------------------------------
// fp32 [K][N] -> bf16 hi/lo [N][K] (transpose + split) for weights
// ---------------------------------------------------------------------------
__global__ __launch_bounds__(256) void split_t_kernel(
    const float* __restrict__ in, __nv_bfloat16* __restrict__ hi,
    __nv_bfloat16* __restrict__ lo, int K, int N)
{
    __shared__ float t[32][33];
    const int tx = threadIdx.x & 31, ty = threadIdx.x >> 5;
    const int n0 = blockIdx.x * 32, k0 = blockIdx.y * 32;
#pragma unroll
    for (int r = 0; r < 4; ++r)
        t[ty + 8 * r][tx] = in[(size_t)(k0 + ty + 8 * r) * N + n0 + tx];
    __syncthreads();
#pragma unroll
    for (int r = 0; r < 4; ++r) {
        const int n = n0 + ty + 8 * r, k = k0 + tx;
        const float x = t[tx][ty + 8 * r];
        const __nv_bfloat16 h = __float2bfloat16_rn(x);
        hi[(size_t)n * K + k] = h;
        lo[(size_t)n * K + k] = __float2bfloat16_rn(x - __bfloat162float(h));
    }
}

// ---------------------------------------------------------------------------
// Per (token, head) LayerNorm of k in-place
// ---------------------------------------------------------------------------
__global__ __launch_bounds__(256) void ln_k_kernel(float* __restrict__ qkv)
{
    using namespace cfg;
    const int gid  = blockIdx.x * blockDim.x + threadIdx.x;
    const int w = gid >> 5, lane = gid & 31;
    const int tok = w >> 4, h = w & 15;
    float* kp = qkv + (size_t)tok * QC + Dm + h * DK;
    float v0 = kp[lane], v1 = kp[lane + 32];
    float s = v0 + v1;
#pragma unroll
    for (int o = 16; o > 0; o >>= 1) s += __shfl_xor_sync(0xffffffffu, s, o);
    const float mu = s * (1.f / 64.f);
    const float d0 = v0 - mu, d1 = v1 - mu;
    float q = d0 * d0 + d1 * d1;
#pragma unroll
    for (int o = 16; o > 0; o >>= 1) q += __shfl_xor_sync(0xffffffffu, q, o);
    const float rstd = rsqrtf(q * (1.f / 64.f) + 1e-5f);
    kp[lane]      = d0 * rstd;
    kp[lane + 32] = d1 * rstd;
}

// ---------------------------------------------------------------------------
// Per-chunk KV outer product
// ---------------------------------------------------------------------------
__global__ __launch_bounds__(256) void chunk_kv_kernel(
    const float* __restrict__ qkv, float* __restrict__ G)
{
    using namespace cfg;
    __shared__ float ks[CH][DK];
    __shared__ float vs[CH][DK];
    const int bid = blockIdx.x;
    const int c = bid & 63, h = (bid >> 6) & 15, b = bid >> 10;
    const int tid = threadIdx.x;
    const float* base = qkv + (size_t)(b * L + c * CH) * QC + h * DK;

    for (int i = tid; i < CH * DK / 4; i += 256) {
        const int t = i >> 4, e4 = (i & 15) << 2;
        *(float4*)&ks[t][e4] = *(const float4*)(base + (size_t)t * QC + Dm + e4);
        *(float4*)&vs[t][e4] = *(const float4*)(base + (size_t)t * QC + 2 * Dm + e4);
    }
    __syncthreads();

    const int dr = (tid >> 4) << 2, ec = (tid & 15) << 2;
    float acc[4][4];
#pragma unroll
    for (int i = 0; i < 4; ++i)
#pragma unroll
        for (int j = 0; j < 4; ++j) acc[i][j] = 0.f;

    for (int t = 0; t < CH; ++t) {
        float4 vv = *(const float4*)&vs[t][dr];
        float4 kk = *(const float4*)&ks[t][ec];
        float va[4] = {vv.x, vv.y, vv.z, vv.w};
        float ka[4] = {kk.x, kk.y, kk.z, kk.w};
#pragma unroll
        for (int i = 0; i < 4; ++i)
#pragma unroll
            for (int j = 0; j < 4; ++j)
                acc[i][j] = fmaf(va[i], ka[j], acc[i][j]);
    }
    float* Gp = G + (size_t)((b * NH + h) * NC + c) * DK * DK;
#pragma unroll
    for (int i = 0; i < 4; ++i)
        *(float4*)(Gp + (size_t)(dr + i) * DK + ec) =
            make_float4(acc[i][0], acc[i][1], acc[i][2], acc[i][3]);
}

// ---------------------------------------------------------------------------
// Exclusive prefix over chunks — one thread per state element
// ---------------------------------------------------------------------------
__global__ __launch_bounds__(256) void prefix_kernel(float* __restrict__ G)
{
    using namespace cfg;
    const int slice = blockIdx.x & 15, bh = blockIdx.x >> 4;
    const int idx = slice * 256 + threadIdx.x;
    float* base = G + (size_t)bh * NC * DK * DK + idx;
    float run = 0.f;
#pragma unroll 4
    for (int c = 0; c < NC; ++c) {
        const float g = base[(size_t)c * DK * DK];
        base[(size_t)c * DK * DK] = run;
        run += g;
    }
}

// ---------------------------------------------------------------------------
// Per-chunk output: y = q_c @ S_c^T + tril(q_c k_c^T) @ v_c
// ---------------------------------------------------------------------------
__global__ __launch_bounds__(256) void attn_kernel(
    const float* __restrict__ qkv, const float* __restrict__ Sx,
    float* __restrict__ y)
{
    using namespace cfg;
    __shared__ float buf0[DK][CH];
    __shared__ float buf1[DK][CH];
    __shared__ float buf2[CH][CH];

    const int bid = blockIdx.x;
    const int c = bid & 63, h = (bid >> 6) & 15, b = bid >> 10;
    const int tid = threadIdx.x;
    const float* base = qkv + (size_t)(b * L + c * CH) * QC + h * DK;

    for (int i = tid; i < CH * DK / 4; i += 256) {
        const int t = i >> 4, e4 = (i & 15) << 2;
        float4 qv = *(const float4*)(base + (size_t)t * QC + e4);
        float4 kv = *(const float4*)(base + (size_t)t * QC + Dm + e4);
        buf0[e4 + 0][t] = qv.x; buf0[e4 + 1][t] = qv.y;
        buf0[e4 + 2][t] = qv.z; buf0[e4 + 3][t] = qv.w;
        buf1[e4 + 0][t] = kv.x; buf1[e4 + 1][t] = kv.y;
        buf1[e4 + 2][t] = kv.z; buf1[e4 + 3][t] = kv.w;
    }
    __syncthreads();

    const int rt = (tid >> 4) << 2, dd = (tid & 15) << 2;

    {
        float sc[4][4];
#pragma unroll
        for (int i = 0; i < 4; ++i)
#pragma unroll
            for (int j = 0; j < 4; ++j) sc[i][j] = 0.f;
        for (int e = 0; e < DK; ++e) {
            float4 q4 = *(const float4*)&buf0[e][rt];
            float4 k4 = *(const float4*)&buf1[e][dd];
            float qa[4] = {q4.x, q4.y, q4.z, q4.w};
            float ka[4] = {k4.x, k4.y, k4.z, k4.w};
#pragma unroll
            for (int i = 0; i < 4; ++i)
#pragma unroll
                for (int j = 0; j < 4; ++j)
                    sc[i][j] = fmaf(qa[i], ka[j], sc[i][j]);
        }
#pragma unroll
        for (int i = 0; i < 4; ++i)
#pragma unroll
            for (int j = 0; j < 4; ++j)
                buf2[dd + j][rt + i] = (dd + j <= rt + i) ? sc[i][j] : 0.f;
    }
    __syncthreads();

    {
        const float* Sp = Sx + (size_t)((b * NH + h) * NC + c) * DK * DK;
        for (int i = tid; i < DK * DK / 4; i += 256) {
            const int d = i >> 4, e4 = (i & 15) << 2;
            float4 sv = *(const float4*)(Sp + (size_t)d * DK + e4);
            buf1[e4 + 0][d] = sv.x; buf1[e4 + 1][d] = sv.y;
            buf1[e4 + 2][d] = sv.z; buf1[e4 + 3][d] = sv.w;
        }
    }
    __syncthreads();

    float acc[4][4];
#pragma unroll
    for (int i = 0; i < 4; ++i)
#pragma unroll
        for (int j = 0; j < 4; ++j) acc[i][j] = 0.f;
    for (int e = 0; e < DK; ++e) {
        float4 q4 = *(const float4*)&buf0[e][rt];
        float4 s4 = *(const float4*)&buf1[e][dd];
        float qa[4] = {q4.x, q4.y, q4.z, q4.w};
        float sa[4] = {s4.x, s4.y, s4.z, s4.w};
#pragma unroll
        for (int i = 0; i < 4; ++i)
#pragma unroll
            for (int j = 0; j < 4; ++j)
                acc[i][j] = fmaf(qa[i], sa[j], acc[i][j]);
    }
    __syncthreads();

    for (int i = tid; i < CH * DK / 4; i += 256) {
        const int t = i >> 4, e4 = (i & 15) << 2;
        *(float4*)&buf0[t][e4] = *(const float4*)(base + (size_t)t * QC + 2 * Dm + e4);
    }
    __syncthreads();

    for (int s = 0; s < CH; ++s) {
        float4 sc4 = *(const float4*)&buf2[s][rt];
        float4 vv4 = *(const float4*)&buf0[s][dd];
        float sa[4] = {sc4.x, sc4.y, sc4.z, sc4.w};
        float va[4] = {vv4.x, vv4.y, vv4.z, vv4.w};
#pragma unroll
        for (int i = 0; i < 4; ++i)
#pragma unroll
            for (int j = 0; j < 4; ++j)
                acc[i][j] = fmaf(sa[i], va[j], acc[i][j]);
    }

    float* yp = y + (size_t)(b * L + c * CH) * Dm + h * DK;
#pragma unroll
    for (int i = 0; i < 4; ++i)
        *(float4*)(yp + (size_t)(rt + i) * Dm + dd) =
            make_float4(acc[i][0], acc[i][1], acc[i][2], acc[i][3]);
}

// ---------------------------------------------------------------------------
// Launcher
// ---------------------------------------------------------------------------
extern "C" void kernel_launch(void* const* d_in, const int* in_sizes, int n_in,
                              void* d_out, int out_size)
{
    using namespace cfg;
    (void)in_sizes; (void)n_in; (void)out_size;
    const float* x    = (const float*)d_in[0];
    const float* Wqkv = (const float*)d_in[1];
    const float* Wo   = (const float*)d_in[2];
    float* out = (float*)d_out;

    float *qkv_p, *st_p, *y_p;
    __nv_bfloat16 *ah, *al, *wqh, *wql, *woh, *wol;
    cudaGetSymbolAddress((void**)&qkv_p, g_qkv);
    cudaGetSymbolAddress((void**)&st_p,  g_state);
    cudaGetSymbolAddress((void**)&y_p,   g_y);
    cudaGetSymbolAddress((void**)&ah,  g_ahi);
    cudaGetSymbolAddress((void**)&al,  g_alo);
    cudaGetSymbolAddress((void**)&wqh, g_wqh);
    cudaGetSymbolAddress((void**)&wql, g_wql);
    cudaGetSymbolAddress((void**)&woh, g_woh);
    cudaGetSymbolAddress((void**)&wol, g_wol);

    static int smem_set = 0;
    if (!smem_set) {
        cudaFuncSetAttribute(gemm_mma_kernel,
                             cudaFuncAttributeMaxDynamicSharedMemorySize, gm::SMEM_SZ);
        smem_set = 1;
    }

    const int n4x = T * Dm / 4;
    // 1) bf16 hi/lo splits (weights transposed to [N][K])
    split_kernel<<<(n4x + 255) / 256, 256>>>(x, ah, al, n4x);
    split_t_kernel<<<dim3(QC / 32, Dm / 32), 256>>>(Wqkv, wqh, wql, Dm, QC);
    split_t_kernel<<<dim3(Dm / 32, Dm / 32), 256>>>(Wo, woh, wol, Dm, Dm);

    // 2) qkv = x @ W_qkv  (HMMA 3x split, 128x256 tile)
    gemm_mma_kernel<<<dim3(QC / 256, T / 128), 256, gm::SMEM_SZ>>>(
        ah, al, wqh, wql, qkv_p, QC, Dm);

    // 3) LN(k), chunk KV, prefix, per-chunk attention
    ln_k_kernel<<<(T * NH) / 8, 256>>>(qkv_p);
    chunk_kv_kernel<<<B * NH * NC, 256>>>(qkv_p, st_p);
    prefix_kernel<<<B * NH * 16, 256>>>(st_p);
    attn_kernel<<<B * NH * NC, 256>>>(qkv_p, st_p, y_p);

    // 4) out = y @ W_o  (HMMA 3x split)
    split_kernel<<<(n4x + 255) / 256, 256>>>(y_p, ah, al, n4x);
    gemm_mma_kernel<<<dim3(Dm / 256, T / 128), 256, gm::SMEM_SZ>>>(
        ah, al, woh, wol, out, Dm, Dm);
}

// round 5
// speedup vs baseline: 1.2280x; 1.2280x over previous
#include <cuda_runtime.h>
#include <cuda_bf16.h>
#include <cstdint>

// ---------------------------------------------------------------------------
// Problem constants
// ---------------------------------------------------------------------------
namespace cfg {
constexpr int Dm   = 1024;
constexpr int NH   = 16;
constexpr int DK   = 64;
constexpr int CH   = 64;
constexpr int B    = 4;
constexpr int L    = 4096;
constexpr int NC   = L / CH;   // 64
constexpr int T    = B * L;    // 16384
constexpr int QC   = 3 * Dm;   // 3072
}

// ---------------------------------------------------------------------------
// Static device scratch
// ---------------------------------------------------------------------------
__device__ float          g_qkv[(size_t)cfg::T * cfg::QC];
__device__ float          g_state[(size_t)cfg::B * cfg::NH * cfg::NC * cfg::DK * cfg::DK];
__device__ float          g_y[(size_t)cfg::T * cfg::Dm];
__device__ __nv_bfloat16  g_ahi[(size_t)cfg::T * cfg::Dm];
__device__ __nv_bfloat16  g_alo[(size_t)cfg::T * cfg::Dm];
__device__ __nv_bfloat16  g_wqh[(size_t)cfg::QC * cfg::Dm];
__device__ __nv_bfloat16  g_wql[(size_t)cfg::QC * cfg::Dm];
__device__ __nv_bfloat16  g_woh[(size_t)cfg::Dm * cfg::Dm];
__device__ __nv_bfloat16  g_wol[(size_t)cfg::Dm * cfg::Dm];

// ---------------------------------------------------------------------------
// PTX helpers
// ---------------------------------------------------------------------------
__device__ __forceinline__ uint32_t smem_u32(const void* p) {
    uint32_t a;
    asm("{ .reg .u64 t; cvta.to.shared.u64 t, %1; cvt.u32.u64 %0, t; }"
        : "=r"(a) : "l"(p));
    return a;
}
#define CP16(dst, src) \
    asm volatile("cp.async.cg.shared.global [%0], [%1], 16;" :: "r"(dst), "l"(src))
#define CP_COMMIT() asm volatile("cp.async.commit_group;" ::: "memory")
#define CP_WAIT(n)  asm volatile("cp.async.wait_group %0;" :: "n"(n) : "memory")

__device__ __forceinline__ void ldsm4(uint32_t* r, uint32_t addr) {
    asm volatile("ldmatrix.sync.aligned.m8n8.x4.shared.b16 {%0,%1,%2,%3}, [%4];"
                 : "=r"(r[0]), "=r"(r[1]), "=r"(r[2]), "=r"(r[3]) : "r"(addr));
}
__device__ __forceinline__ void mma16816(float* c, const uint32_t* a, const uint32_t* b) {
    asm volatile(
        "mma.sync.aligned.m16n8k16.row.col.f32.bf16.bf16.f32 "
        "{%0,%1,%2,%3}, {%4,%5,%6,%7}, {%8,%9}, {%0,%1,%2,%3};"
        : "+f"(c[0]), "+f"(c[1]), "+f"(c[2]), "+f"(c[3])
        : "r"(a[0]), "r"(a[1]), "r"(a[2]), "r"(a[3]), "r"(b[0]), "r"(b[1]));
}

// ---------------------------------------------------------------------------
// bf16 3x-split GEMM via HMMA:
//   C[M,N](fp32) = Ah@Bh^T + Ah@Bl^T + Al@Bh^T
//   A*: [M,K] bf16 row-major. B*: [N,K] bf16 row-major (pre-transposed W).
//   CTA tile 128x128, 512 threads, warp grid 4x4 (warp tile 32x32).
//   K-chunk = 64 halves (128B rows), swizzle c ^= (row & 7).
//   2-stage cp.async (128 KiB). 16 warps/SM -> 4 eligible warps per SMSP.
// ---------------------------------------------------------------------------
namespace gm {
constexpr int TILE_B  = 128 * 128;          // 16 KiB per operand tile
constexpr int STAGE_B = 4 * TILE_B;         // 64 KiB (Ah, Al, Bh, Bl)
constexpr int SMEM_SZ = 2 * STAGE_B;        // 128 KiB
}

__global__ __launch_bounds__(512, 1) void gemm_mma_kernel(
    const __nv_bfloat16* __restrict__ Ah, const __nv_bfloat16* __restrict__ Al,
    const __nv_bfloat16* __restrict__ Bh, const __nv_bfloat16* __restrict__ Bl,
    float* __restrict__ C, int N, int K)
{
    extern __shared__ char smem[];
    const uint32_t sb = smem_u32(smem);
    const int tid = threadIdx.x, wid = tid >> 5, lane = tid & 31;
    const int tn = blockIdx.x, tm = blockIdx.y;
    const int wm = wid >> 2;   // 0..3 : 32-row slab
    const int wn = wid & 3;    // 0..3 : 32-col slab

    const __nv_bfloat16* aA[2] = { Ah + (size_t)tm * 128 * K, Al + (size_t)tm * 128 * K };
    const __nv_bfloat16* bB[2] = { Bh + (size_t)tn * 128 * K, Bl + (size_t)tn * 128 * K };

    // staging: 4 threads/row, 2 chunks (32B) each
    const int lrow = tid >> 2;          // 0..127
    const int lc0  = (tid & 3) * 2;     // 0,2,4,6

    auto load_stage = [&](int chunk, int stage) {
        const uint32_t st = sb + stage * gm::STAGE_B;
#pragma unroll
        for (int t2 = 0; t2 < 2; ++t2) {
            const __nv_bfloat16* pa = aA[t2] + (size_t)lrow * K + chunk * 64;
            const __nv_bfloat16* pb = bB[t2] + (size_t)lrow * K + chunk * 64;
            const uint32_t da = st + t2 * gm::TILE_B + lrow * 128;
            const uint32_t db = st + (2 + t2) * gm::TILE_B + lrow * 128;
#pragma unroll
            for (int cc = 0; cc < 2; ++cc) {
                const int c = lc0 + cc;
                const uint32_t so = (c ^ (lrow & 7)) * 16;
                CP16(da + so, pa + c * 8);
                CP16(db + so, pb + c * 8);
            }
        }
    };

    float acc[2][4][4];
#pragma unroll
    for (int t = 0; t < 2; ++t)
#pragma unroll
        for (int j = 0; j < 4; ++j)
#pragma unroll
            for (int r = 0; r < 4; ++r) acc[t][j][r] = 0.f;

    const int NK = K >> 6;
    load_stage(0, 0); CP_COMMIT();
    load_stage(1, 1); CP_COMMIT();

    for (int i = 0; i < NK; ++i) {
        CP_WAIT(1);
        __syncthreads();

        const uint32_t st  = sb + (i & 1) * gm::STAGE_B;
        const uint32_t ahB = st;
        const uint32_t alB = st + gm::TILE_B;
        const uint32_t bhB = st + 2 * gm::TILE_B;
        const uint32_t blB = st + 3 * gm::TILE_B;

#pragma unroll
        for (int s = 0; s < 4; ++s) {          // k16 steps within 64-half chunk
            uint32_t ah[2][4], al[2][4];
#pragma unroll
            for (int t = 0; t < 2; ++t) {
                const int row = wm * 32 + t * 16 + (lane & 15);
                const int c   = s * 2 + (lane >> 4);
                const uint32_t off = row * 128 + ((c ^ (row & 7)) * 16);
                ldsm4(ah[t], ahB + off);
                ldsm4(al[t], alB + off);
            }
            uint32_t bh[4][2], bl[4][2];
#pragma unroll
            for (int p = 0; p < 2; ++p) {      // 2 ldsm cover 4 n8-tiles
                const int row = wn * 32 + p * 16 + ((lane & 16) >> 1) + (lane & 7);
                const int c   = s * 2 + ((lane >> 3) & 1);
                const uint32_t off = row * 128 + ((c ^ (row & 7)) * 16);
                uint32_t r[4];
                ldsm4(r, bhB + off);
                bh[2 * p][0] = r[0]; bh[2 * p][1] = r[1];
                bh[2 * p + 1][0] = r[2]; bh[2 * p + 1][1] = r[3];
                ldsm4(r, blB + off);
                bl[2 * p][0] = r[0]; bl[2 * p][1] = r[1];
                bl[2 * p + 1][0] = r[2]; bl[2 * p + 1][1] = r[3];
            }
#pragma unroll
            for (int t = 0; t < 2; ++t)
#pragma unroll
                for (int j = 0; j < 4; ++j) {
                    mma16816(acc[t][j], ah[t], bh[j]);
                    mma16816(acc[t][j], ah[t], bl[j]);
                    mma16816(acc[t][j], al[t], bh[j]);
                }
        }
        __syncthreads();
        if (i + 2 < NK) load_stage(i + 2, (i & 1));
        CP_COMMIT();
    }

    // epilogue
    const int qr = lane >> 2, qc = (lane & 3) * 2;
#pragma unroll
    for (int t = 0; t < 2; ++t) {
        const int r0 = tm * 128 + wm * 32 + t * 16 + qr;
#pragma unroll
        for (int j = 0; j < 4; ++j) {
            const int col = tn * 128 + wn * 32 + j * 8 + qc;
            *(float2*)(C + (size_t)r0 * N + col)       = make_float2(acc[t][j][0], acc[t][j][1]);
            *(float2*)(C + (size_t)(r0 + 8) * N + col) = make_float2(acc[t][j][2], acc[t][j][3]);
        }
    }
}

// ---------------------------------------------------------------------------
// fp32 -> bf16 hi/lo split
// ---------------------------------------------------------------------------
__global__ __launch_bounds__(256) void split_kernel(
    const float* __restrict__ in, __nv_bfloat16* __restrict__ hi,
    __nv_bfloat16* __restrict__ lo, int n4)
{
    const int i = blockIdx.x * 256 + threadIdx.x;
    if (i >= n4) return;
    const float4 v = *(const float4*)(in + (size_t)i * 4);
    float xs[4] = {v.x, v.y, v.z, v.w};
    __nv_bfloat16 h[4], l[4];
#pragma unroll
    for (int j = 0; j < 4; ++j) {
        h[j] = __float2bfloat16_rn(xs[j]);
        l[j] = __float2bfloat16_rn(xs[j] - __bfloat162float(h[j]));
    }
    *(__nv_bfloat162*)(hi + (size_t)i * 4)     = __nv_bfloat162(h[0], h[1]);
    *(__nv_bfloat162*)(hi + (size_t)i * 4 + 2) = __nv_bfloat162(h[2], h[3]);
    *(__nv_bfloat162*)(lo + (size_t)i * 4)     = __nv_bfloat162(l[0], l[1]);
    *(__nv_bfloat162*)(lo + (size_t)i * 4 + 2) = __nv_bfloat162(l[2], l[3]);
}

// ---------------------------------------------------------------------------
// fp32 [K][N] -> bf16 hi/lo [N][K] (transpose + split) for weights
// ---------------------------------------------------------------------------
__global__ __launch_bounds__(256) void split_t_kernel(
    const float* __restrict__ in, __nv_bfloat16* __restrict__ hi,
    __nv_bfloat16* __restrict__ lo, int K, int N)
{
    __shared__ float t[32][33];
    const int tx = threadIdx.x & 31, ty = threadIdx.x >> 5;
    const int n0 = blockIdx.x * 32, k0 = blockIdx.y * 32;
#pragma unroll
    for (int r = 0; r < 4; ++r)
        t[ty + 8 * r][tx] = in[(size_t)(k0 + ty + 8 * r) * N + n0 + tx];
    __syncthreads();
#pragma unroll
    for (int r = 0; r < 4; ++r) {
        const int n = n0 + ty + 8 * r, k = k0 + tx;
        const float x = t[tx][ty + 8 * r];
        const __nv_bfloat16 h = __float2bfloat16_rn(x);
        hi[(size_t)n * K + k] = h;
        lo[(size_t)n * K + k] = __float2bfloat16_rn(x - __bfloat162float(h));
    }
}

// ---------------------------------------------------------------------------
// Per (token, head) LayerNorm of k in-place
// ---------------------------------------------------------------------------
__global__ __launch_bounds__(256) void ln_k_kernel(float* __restrict__ qkv)
{
    using namespace cfg;
    const int gid  = blockIdx.x * blockDim.x + threadIdx.x;
    const int w = gid >> 5, lane = gid & 31;
    const int tok = w >> 4, h = w & 15;
    float* kp = qkv + (size_t)tok * QC + Dm + h * DK;
    float v0 = kp[lane], v1 = kp[lane + 32];
    float s = v0 + v1;
#pragma unroll
    for (int o = 16; o > 0; o >>= 1) s += __shfl_xor_sync(0xffffffffu, s, o);
    const float mu = s * (1.f / 64.f);
    const float d0 = v0 - mu, d1 = v1 - mu;
    float q = d0 * d0 + d1 * d1;
#pragma unroll
    for (int o = 16; o > 0; o >>= 1) q += __shfl_xor_sync(0xffffffffu, q, o);
    const float rstd = rsqrtf(q * (1.f / 64.f) + 1e-5f);
    kp[lane]      = d0 * rstd;
    kp[lane + 32] = d1 * rstd;
}

// ---------------------------------------------------------------------------
// Per-chunk KV outer product
// ---------------------------------------------------------------------------
__global__ __launch_bounds__(256) void chunk_kv_kernel(
    const float* __restrict__ qkv, float* __restrict__ G)
{
    using namespace cfg;
    __shared__ float ks[CH][DK];
    __shared__ float vs[CH][DK];
    const int bid = blockIdx.x;
    const int c = bid & 63, h = (bid >> 6) & 15, b = bid >> 10;
    const int tid = threadIdx.x;
    const float* base = qkv + (size_t)(b * L + c * CH) * QC + h * DK;

    for (int i = tid; i < CH * DK / 4; i += 256) {
        const int t = i >> 4, e4 = (i & 15) << 2;
        *(float4*)&ks[t][e4] = *(const float4*)(base + (size_t)t * QC + Dm + e4);
        *(float4*)&vs[t][e4] = *(const float4*)(base + (size_t)t * QC + 2 * Dm + e4);
    }
    __syncthreads();

    const int dr = (tid >> 4) << 2, ec = (tid & 15) << 2;
    float acc[4][4];
#pragma unroll
    for (int i = 0; i < 4; ++i)
#pragma unroll
        for (int j = 0; j < 4; ++j) acc[i][j] = 0.f;

    for (int t = 0; t < CH; ++t) {
        float4 vv = *(const float4*)&vs[t][dr];
        float4 kk = *(const float4*)&ks[t][ec];
        float va[4] = {vv.x, vv.y, vv.z, vv.w};
        float ka[4] = {kk.x, kk.y, kk.z, kk.w};
#pragma unroll
        for (int i = 0; i < 4; ++i)
#pragma unroll
            for (int j = 0; j < 4; ++j)
                acc[i][j] = fmaf(va[i], ka[j], acc[i][j]);
    }
    float* Gp = G + (size_t)((b * NH + h) * NC + c) * DK * DK;
#pragma unroll
    for (int i = 0; i < 4; ++i)
        *(float4*)(Gp + (size_t)(dr + i) * DK + ec) =
            make_float4(acc[i][0], acc[i][1], acc[i][2], acc[i][3]);
}

// ---------------------------------------------------------------------------
// Exclusive prefix over chunks — one thread per state element
// ---------------------------------------------------------------------------
__global__ __launch_bounds__(256) void prefix_kernel(float* __restrict__ G)
{
    using namespace cfg;
    const int slice = blockIdx.x & 15, bh = blockIdx.x >> 4;
    const int idx = slice * 256 + threadIdx.x;
    float* base = G + (size_t)bh * NC * DK * DK + idx;
    float run = 0.f;
#pragma unroll 4
    for (int c = 0; c < NC; ++c) {
        const float g = base[(size_t)c * DK * DK];
        base[(size_t)c * DK * DK] = run;
        run += g;
    }
}

// ---------------------------------------------------------------------------
// Per-chunk output: y = q_c @ S_c^T + tril(q_c k_c^T) @ v_c
// ---------------------------------------------------------------------------
__global__ __launch_bounds__(256) void attn_kernel(
    const float* __restrict__ qkv, const float* __restrict__ Sx,
    float* __restrict__ y)
{
    using namespace cfg;
    __shared__ float buf0[DK][CH];
    __shared__ float buf1[DK][CH];
    __shared__ float buf2[CH][CH];

    const int bid = blockIdx.x;
    const int c = bid & 63, h = (bid >> 6) & 15, b = bid >> 10;
    const int tid = threadIdx.x;
    const float* base = qkv + (size_t)(b * L + c * CH) * QC + h * DK;

    for (int i = tid; i < CH * DK / 4; i += 256) {
        const int t = i >> 4, e4 = (i & 15) << 2;
        float4 qv = *(const float4*)(base + (size_t)t * QC + e4);
        float4 kv = *(const float4*)(base + (size_t)t * QC + Dm + e4);
        buf0[e4 + 0][t] = qv.x; buf0[e4 + 1][t] = qv.y;
        buf0[e4 + 2][t] = qv.z; buf0[e4 + 3][t] = qv.w;
        buf1[e4 + 0][t] = kv.x; buf1[e4 + 1][t] = kv.y;
        buf1[e4 + 2][t] = kv.z; buf1[e4 + 3][t] = kv.w;
    }
    __syncthreads();

    const int rt = (tid >> 4) << 2, dd = (tid & 15) << 2;

    {
        float sc[4][4];
#pragma unroll
        for (int i = 0; i < 4; ++i)
#pragma unroll
            for (int j = 0; j < 4; ++j) sc[i][j] = 0.f;
        for (int e = 0; e < DK; ++e) {
            float4 q4 = *(const float4*)&buf0[e][rt];
            float4 k4 = *(const float4*)&buf1[e][dd];
            float qa[4] = {q4.x, q4.y, q4.z, q4.w};
            float ka[4] = {k4.x, k4.y, k4.z, k4.w};
#pragma unroll
            for (int i = 0; i < 4; ++i)
#pragma unroll
                for (int j = 0; j < 4; ++j)
                    sc[i][j] = fmaf(qa[i], ka[j], sc[i][j]);
        }
#pragma unroll
        for (int i = 0; i < 4; ++i)
#pragma unroll
            for (int j = 0; j < 4; ++j)
                buf2[dd + j][rt + i] = (dd + j <= rt + i) ? sc[i][j] : 0.f;
    }
    __syncthreads();

    {
        const float* Sp = Sx + (size_t)((b * NH + h) * NC + c) * DK * DK;
        for (int i = tid; i < DK * DK / 4; i += 256) {
            const int d = i >> 4, e4 = (i & 15) << 2;
            float4 sv = *(const float4*)(Sp + (size_t)d * DK + e4);
            buf1[e4 + 0][d] = sv.x; buf1[e4 + 1][d] = sv.y;
            buf1[e4 + 2][d] = sv.z; buf1[e4 + 3][d] = sv.w;
        }
    }
    __syncthreads();

    float acc[4][4];
#pragma unroll
    for (int i = 0; i < 4; ++i)
#pragma unroll
        for (int j = 0; j < 4; ++j) acc[i][j] = 0.f;
    for (int e = 0; e < DK; ++e) {
        float4 q4 = *(const float4*)&buf0[e][rt];
        float4 s4 = *(const float4*)&buf1[e][dd];
        float qa[4] = {q4.x, q4.y, q4.z, q4.w};
        float sa[4] = {s4.x, s4.y, s4.z, s4.w};
#pragma unroll
        for (int i = 0; i < 4; ++i)
#pragma unroll
            for (int j = 0; j < 4; ++j)
                acc[i][j] = fmaf(qa[i], sa[j], acc[i][j]);
    }
    __syncthreads();

    for (int i = tid; i < CH * DK / 4; i += 256) {
        const int t = i >> 4, e4 = (i & 15) << 2;
        *(float4*)&buf0[t][e4] = *(const float4*)(base + (size_t)t * QC + 2 * Dm + e4);
    }
    __syncthreads();

    for (int s = 0; s < CH; ++s) {
        float4 sc4 = *(const float4*)&buf2[s][rt];
        float4 vv4 = *(const float4*)&buf0[s][dd];
        float sa[4] = {sc4.x, sc4.y, sc4.z, sc4.w};
        float va[4] = {vv4.x, vv4.y, vv4.z, vv4.w};
#pragma unroll
        for (int i = 0; i < 4; ++i)
#pragma unroll
            for (int j = 0; j < 4; ++j)
                acc[i][j] = fmaf(sa[i], va[j], acc[i][j]);
    }

    float* yp = y + (size_t)(b * L + c * CH) * Dm + h * DK;
#pragma unroll
    for (int i = 0; i < 4; ++i)
        *(float4*)(yp + (size_t)(rt + i) * Dm + dd) =
            make_float4(acc[i][0], acc[i][1], acc[i][2], acc[i][3]);
}

// ---------------------------------------------------------------------------
// Launcher
// ---------------------------------------------------------------------------
extern "C" void kernel_launch(void* const* d_in, const int* in_sizes, int n_in,
                              void* d_out, int out_size)
{
    using namespace cfg;
    (void)in_sizes; (void)n_in; (void)out_size;
    const float* x    = (const float*)d_in[0];
    const float* Wqkv = (const float*)d_in[1];
    const float* Wo   = (const float*)d_in[2];
    float* out = (float*)d_out;

    float *qkv_p, *st_p, *y_p;
    __nv_bfloat16 *ah, *al, *wqh, *wql, *woh, *wol;
    cudaGetSymbolAddress((void**)&qkv_p, g_qkv);
    cudaGetSymbolAddress((void**)&st_p,  g_state);
    cudaGetSymbolAddress((void**)&y_p,   g_y);
    cudaGetSymbolAddress((void**)&ah,  g_ahi);
    cudaGetSymbolAddress((void**)&al,  g_alo);
    cudaGetSymbolAddress((void**)&wqh, g_wqh);
    cudaGetSymbolAddress((void**)&wql, g_wql);
    cudaGetSymbolAddress((void**)&woh, g_woh);
    cudaGetSymbolAddress((void**)&wol, g_wol);

    static int smem_set = 0;
    if (!smem_set) {
        cudaFuncSetAttribute(gemm_mma_kernel,
                             cudaFuncAttributeMaxDynamicSharedMemorySize, gm::SMEM_SZ);
        smem_set = 1;
    }

    const int n4x = T * Dm / 4;
    // 1) bf16 hi/lo splits (weights transposed to [N][K])
    split_kernel<<<(n4x + 255) / 256, 256>>>(x, ah, al, n4x);
    split_t_kernel<<<dim3(QC / 32, Dm / 32), 256>>>(Wqkv, wqh, wql, Dm, QC);
    split_t_kernel<<<dim3(Dm / 32, Dm / 32), 256>>>(Wo, woh, wol, Dm, Dm);

    // 2) qkv = x @ W_qkv  (HMMA 3x split, 128x128 tile, 512 thr)
    gemm_mma_kernel<<<dim3(QC / 128, T / 128), 512, gm::SMEM_SZ>>>(
        ah, al, wqh, wql, qkv_p, QC, Dm);

    // 3) LN(k), chunk KV, prefix, per-chunk attention
    ln_k_kernel<<<(T * NH) / 8, 256>>>(qkv_p);
    chunk_kv_kernel<<<B * NH * NC, 256>>>(qkv_p, st_p);
    prefix_kernel<<<B * NH * 16, 256>>>(st_p);
    attn_kernel<<<B * NH * NC, 256>>>(qkv_p, st_p, y_p);

    // 4) out = y @ W_o  (HMMA 3x split)
    split_kernel<<<(n4x + 255) / 256, 256>>>(y_p, ah, al, n4x);
    gemm_mma_kernel<<<dim3(Dm / 128, T / 128), 512, gm::SMEM_SZ>>>(
        ah, al, woh, wol, out, Dm, Dm);
}

// round 6
// speedup vs baseline: 1.4613x; 1.1900x over previous
#include <cuda_runtime.h>
#include <cuda_bf16.h>
#include <cstdint>

// ---------------------------------------------------------------------------
// Problem constants
// ---------------------------------------------------------------------------
namespace cfg {
constexpr int Dm   = 1024;
constexpr int NH   = 16;
constexpr int DK   = 64;
constexpr int CH   = 64;
constexpr int B    = 4;
constexpr int L    = 4096;
constexpr int NC   = L / CH;   // 64
constexpr int T    = B * L;    // 16384
constexpr int QC   = 3 * Dm;   // 3072
constexpr int NT   = B * NH * NC;       // 4096 tiles
constexpr int TS   = CH * DK;           // 4096 elems / tile
}

// ---------------------------------------------------------------------------
// Static device scratch
// ---------------------------------------------------------------------------
__device__ float          g_qkv[(size_t)cfg::T * cfg::QC];                  // 192 MiB
__device__ float          g_state[(size_t)cfg::NT * cfg::TS];               // 64 MiB
__device__ __nv_bfloat16  g_ahi[(size_t)cfg::T * cfg::Dm];                  // x / y hi
__device__ __nv_bfloat16  g_alo[(size_t)cfg::T * cfg::Dm];                  // x / y lo
__device__ __nv_bfloat16  g_wqh[(size_t)cfg::QC * cfg::Dm];
__device__ __nv_bfloat16  g_wql[(size_t)cfg::QC * cfg::Dm];
__device__ __nv_bfloat16  g_woh[(size_t)cfg::Dm * cfg::Dm];
__device__ __nv_bfloat16  g_wol[(size_t)cfg::Dm * cfg::Dm];
// chunk tiles, [b][h][c][64][64] each, bf16 hi/lo
__device__ __nv_bfloat16  g_qh[(size_t)cfg::NT * cfg::TS];
__device__ __nv_bfloat16  g_ql[(size_t)cfg::NT * cfg::TS];
__device__ __nv_bfloat16  g_kh[(size_t)cfg::NT * cfg::TS];   // k  [t][e]
__device__ __nv_bfloat16  g_kl[(size_t)cfg::NT * cfg::TS];
__device__ __nv_bfloat16  g_kth[(size_t)cfg::NT * cfg::TS];  // k^T [e][t]
__device__ __nv_bfloat16  g_ktl[(size_t)cfg::NT * cfg::TS];
__device__ __nv_bfloat16  g_vth[(size_t)cfg::NT * cfg::TS];  // v^T [d][t]
__device__ __nv_bfloat16  g_vtl[(size_t)cfg::NT * cfg::TS];
__device__ __nv_bfloat16  g_sh[(size_t)cfg::NT * cfg::TS];   // S   [d][e]
__device__ __nv_bfloat16  g_sl[(size_t)cfg::NT * cfg::TS];

// ---------------------------------------------------------------------------
// PTX helpers
// ---------------------------------------------------------------------------
__device__ __forceinline__ uint32_t smem_u32(const void* p) {
    uint32_t a;
    asm("{ .reg .u64 t; cvta.to.shared.u64 t, %1; cvt.u32.u64 %0, t; }"
        : "=r"(a) : "l"(p));
    return a;
}
#define CP16(dst, src) \
    asm volatile("cp.async.cg.shared.global [%0], [%1], 16;" :: "r"(dst), "l"(src))
#define CP_COMMIT() asm volatile("cp.async.commit_group;" ::: "memory")
#define CP_WAIT(n)  asm volatile("cp.async.wait_group %0;" :: "n"(n) : "memory")

__device__ __forceinline__ void ldsm4(uint32_t* r, uint32_t addr) {
    asm volatile("ldmatrix.sync.aligned.m8n8.x4.shared.b16 {%0,%1,%2,%3}, [%4];"
                 : "=r"(r[0]), "=r"(r[1]), "=r"(r[2]), "=r"(r[3]) : "r"(addr));
}
__device__ __forceinline__ void mma16816(float* c, const uint32_t* a, const uint32_t* b) {
    asm volatile(
        "mma.sync.aligned.m16n8k16.row.col.f32.bf16.bf16.f32 "
        "{%0,%1,%2,%3}, {%4,%5,%6,%7}, {%8,%9}, {%0,%1,%2,%3};"
        : "+f"(c[0]), "+f"(c[1]), "+f"(c[2]), "+f"(c[3])
        : "r"(a[0]), "r"(a[1]), "r"(a[2]), "r"(a[3]), "r"(b[0]), "r"(b[1]));
}
__device__ __forceinline__ void split2(float x, __nv_bfloat16& h, __nv_bfloat16& l) {
    h = __float2bfloat16_rn(x);
    l = __float2bfloat16_rn(x - __bfloat162float(h));
}

// ---------------------------------------------------------------------------
// 64x64x64 hi/lo 3-pass MMA block op (4 warps, warp = 16 M-rows x 64 N).
// All tiles: 64 rows x 128B smem, swizzle chunk ^= (row & 7).
//   acc[j][r] += Ah@Bh^T + Ah@Bl^T + Al@Bh^T   (A:[M][K], B:[N][K])
// ---------------------------------------------------------------------------
__device__ __forceinline__ void mma64_3pass(
    float acc[8][4], uint32_t aH, uint32_t aL, uint32_t bH, uint32_t bL,
    int wm, int lane)
{
#pragma unroll
    for (int s = 0; s < 4; ++s) {
        uint32_t ah[4], al[4];
        {
            const int arow = wm * 16 + (lane & 15);
            const int ac   = s * 2 + (lane >> 4);
            const uint32_t aoff = arow * 128 + ((ac ^ (arow & 7)) * 16);
            ldsm4(ah, aH + aoff);
            ldsm4(al, aL + aoff);
        }
        uint32_t bh[8][2], bl[8][2];
#pragma unroll
        for (int p = 0; p < 4; ++p) {
            const int brow = p * 16 + ((lane & 16) >> 1) + (lane & 7);
            const int bc   = s * 2 + ((lane >> 3) & 1);
            const uint32_t boff = brow * 128 + ((bc ^ (brow & 7)) * 16);
            uint32_t r[4];
            ldsm4(r, bH + boff);
            bh[2 * p][0] = r[0]; bh[2 * p][1] = r[1];
            bh[2 * p + 1][0] = r[2]; bh[2 * p + 1][1] = r[3];
            ldsm4(r, bL + boff);
            bl[2 * p][0] = r[0]; bl[2 * p][1] = r[1];
            bl[2 * p + 1][0] = r[2]; bl[2 * p + 1][1] = r[3];
        }
#pragma unroll
        for (int j = 0; j < 8; ++j) {
            mma16816(acc[j], ah, bh[j]);
            mma16816(acc[j], ah, bl[j]);
            mma16816(acc[j], al, bh[j]);
        }
    }
}

// load one 64x128B bf16 tile into swizzled smem (128 threads, 4 CP16 each)
__device__ __forceinline__ void cp_tile_128(
    uint32_t dst, const __nv_bfloat16* src, int tid)
{
    const int row = tid >> 1, c0 = (tid & 1) * 4;
#pragma unroll
    for (int cc = 0; cc < 4; ++cc) {
        const int c = c0 + cc;
        CP16(dst + row * 128 + ((c ^ (row & 7)) * 16), src + row * 64 + c * 8);
    }
}

// ---------------------------------------------------------------------------
// Main GEMM: C[M,N](fp32) = Ah@Bh^T + Ah@Bl^T + Al@Bh^T  (HMMA, 3-stage)
// CTA 128x128, 512 thr, warp 32x32. One __syncthreads per K-iter; loads
// issued before compute.
// ---------------------------------------------------------------------------
namespace gm {
constexpr int TILE_B  = 128 * 128;
constexpr int STAGE_B = 4 * TILE_B;          // 64 KiB
constexpr int SMEM_SZ = 3 * STAGE_B;         // 192 KiB
}

__global__ __launch_bounds__(512, 1) void gemm_mma_kernel(
    const __nv_bfloat16* __restrict__ Ah, const __nv_bfloat16* __restrict__ Al,
    const __nv_bfloat16* __restrict__ Bh, const __nv_bfloat16* __restrict__ Bl,
    float* __restrict__ C, int N, int K)
{
    extern __shared__ char smem[];
    const uint32_t sb = smem_u32(smem);
    const int tid = threadIdx.x, wid = tid >> 5, lane = tid & 31;
    const int tn = blockIdx.x, tm = blockIdx.y;
    const int wm = wid >> 2, wn = wid & 3;

    const __nv_bfloat16* aA[2] = { Ah + (size_t)tm * 128 * K, Al + (size_t)tm * 128 * K };
    const __nv_bfloat16* bB[2] = { Bh + (size_t)tn * 128 * K, Bl + (size_t)tn * 128 * K };

    const int lrow = tid >> 2, lc0 = (tid & 3) * 2;

    auto load_stage = [&](int chunk, int stage) {
        const uint32_t st = sb + stage * gm::STAGE_B;
#pragma unroll
        for (int t2 = 0; t2 < 2; ++t2) {
            const __nv_bfloat16* pa = aA[t2] + (size_t)lrow * K + chunk * 64;
            const __nv_bfloat16* pb = bB[t2] + (size_t)lrow * K + chunk * 64;
            const uint32_t da = st + t2 * gm::TILE_B + lrow * 128;
            const uint32_t db = st + (2 + t2) * gm::TILE_B + lrow * 128;
#pragma unroll
            for (int cc = 0; cc < 2; ++cc) {
                const int c = lc0 + cc;
                const uint32_t so = (c ^ (lrow & 7)) * 16;
                CP16(da + so, pa + c * 8);
                CP16(db + so, pb + c * 8);
            }
        }
    };

    float acc[2][4][4];
#pragma unroll
    for (int t = 0; t < 2; ++t)
#pragma unroll
        for (int j = 0; j < 4; ++j)
#pragma unroll
            for (int r = 0; r < 4; ++r) acc[t][j][r] = 0.f;

    const int NK = K >> 6;
    load_stage(0, 0); CP_COMMIT();
    load_stage(1, 1); CP_COMMIT();

    for (int i = 0; i < NK; ++i) {
        CP_WAIT(1);                 // chunk i landed
        __syncthreads();            // and everyone finished reading buf (i+2)%3
        if (i + 2 < NK) load_stage(i + 2, (i + 2) % 3);
        CP_COMMIT();                // uniform group count

        const uint32_t st  = sb + (i % 3) * gm::STAGE_B;
        const uint32_t ahB = st;
        const uint32_t alB = st + gm::TILE_B;
        const uint32_t bhB = st + 2 * gm::TILE_B;
        const uint32_t blB = st + 3 * gm::TILE_B;

#pragma unroll
        for (int s = 0; s < 4; ++s) {
            uint32_t ah[2][4], al[2][4];
#pragma unroll
            for (int t = 0; t < 2; ++t) {
                const int row = wm * 32 + t * 16 + (lane & 15);
                const int c   = s * 2 + (lane >> 4);
                const uint32_t off = row * 128 + ((c ^ (row & 7)) * 16);
                ldsm4(ah[t], ahB + off);
                ldsm4(al[t], alB + off);
            }
            uint32_t bh[4][2], bl[4][2];
#pragma unroll
            for (int p = 0; p < 2; ++p) {
                const int row = wn * 32 + p * 16 + ((lane & 16) >> 1) + (lane & 7);
                const int c   = s * 2 + ((lane >> 3) & 1);
                const uint32_t off = row * 128 + ((c ^ (row & 7)) * 16);
                uint32_t r[4];
                ldsm4(r, bhB + off);
                bh[2 * p][0] = r[0]; bh[2 * p][1] = r[1];
                bh[2 * p + 1][0] = r[2]; bh[2 * p + 1][1] = r[3];
                ldsm4(r, blB + off);
                bl[2 * p][0] = r[0]; bl[2 * p][1] = r[1];
                bl[2 * p + 1][0] = r[2]; bl[2 * p + 1][1] = r[3];
            }
#pragma unroll
            for (int t = 0; t < 2; ++t)
#pragma unroll
                for (int j = 0; j < 4; ++j) {
                    mma16816(acc[t][j], ah[t], bh[j]);
                    mma16816(acc[t][j], ah[t], bl[j]);
                    mma16816(acc[t][j], al[t], bh[j]);
                }
        }
    }

    const int qr = lane >> 2, qc = (lane & 3) * 2;
#pragma unroll
    for (int t = 0; t < 2; ++t) {
        const int r0 = tm * 128 + wm * 32 + t * 16 + qr;
#pragma unroll
        for (int j = 0; j < 4; ++j) {
            const int col = tn * 128 + wn * 32 + j * 8 + qc;
            *(float2*)(C + (size_t)r0 * N + col)       = make_float2(acc[t][j][0], acc[t][j][1]);
            *(float2*)(C + (size_t)(r0 + 8) * N + col) = make_float2(acc[t][j][2], acc[t][j][3]);
        }
    }
}

// ---------------------------------------------------------------------------
// splits for x and weights
// ---------------------------------------------------------------------------
__global__ __launch_bounds__(256) void split_kernel(
    const float* __restrict__ in, __nv_bfloat16* __restrict__ hi,
    __nv_bfloat16* __restrict__ lo, int n4)
{
    const int i = blockIdx.x * 256 + threadIdx.x;
    if (i >= n4) return;
    const float4 v = *(const float4*)(in + (size_t)i * 4);
    float xs[4] = {v.x, v.y, v.z, v.w};
    __nv_bfloat16 h[4], l[4];
#pragma unroll
    for (int j = 0; j < 4; ++j) split2(xs[j], h[j], l[j]);
    *(__nv_bfloat162*)(hi + (size_t)i * 4)     = __nv_bfloat162(h[0], h[1]);
    *(__nv_bfloat162*)(hi + (size_t)i * 4 + 2) = __nv_bfloat162(h[2], h[3]);
    *(__nv_bfloat162*)(lo + (size_t)i * 4)     = __nv_bfloat162(l[0], l[1]);
    *(__nv_bfloat162*)(lo + (size_t)i * 4 + 2) = __nv_bfloat162(l[2], l[3]);
}

__global__ __launch_bounds__(256) void split_t_kernel(
    const float* __restrict__ in, __nv_bfloat16* __restrict__ hi,
    __nv_bfloat16* __restrict__ lo, int K, int N)
{
    __shared__ float t[32][33];
    const int tx = threadIdx.x & 31, ty = threadIdx.x >> 5;
    const int n0 = blockIdx.x * 32, k0 = blockIdx.y * 32;
#pragma unroll
    for (int r = 0; r < 4; ++r)
        t[ty + 8 * r][tx] = in[(size_t)(k0 + ty + 8 * r) * N + n0 + tx];
    __syncthreads();
#pragma unroll
    for (int r = 0; r < 4; ++r) {
        const int n = n0 + ty + 8 * r, k = k0 + tx;
        const float x = t[tx][ty + 8 * r];
        __nv_bfloat16 h, l; split2(x, h, l);
        hi[(size_t)n * K + k] = h;
        lo[(size_t)n * K + k] = l;
    }
}

// ---------------------------------------------------------------------------
// postproc: per (b,h,c) tile — LN(k), bf16 hi/lo splits, transposes.
// Outputs: q[t][e], k[t][e], kT[e][t], vT[d][t]  (hi/lo each)
// 256 threads per block.
// ---------------------------------------------------------------------------
__global__ __launch_bounds__(256) void postproc_kernel(
    const float* __restrict__ qkv,
    __nv_bfloat16* __restrict__ qh, __nv_bfloat16* __restrict__ ql,
    __nv_bfloat16* __restrict__ kh, __nv_bfloat16* __restrict__ kl,
    __nv_bfloat16* __restrict__ kth, __nv_bfloat16* __restrict__ ktl,
    __nv_bfloat16* __restrict__ vth, __nv_bfloat16* __restrict__ vtl)
{
    using namespace cfg;
    __shared__ float tile[64][65];
    const int bid = blockIdx.x;
    const int c = bid & 63, h = (bid >> 6) & 15, b = bid >> 10;
    const int tid = threadIdx.x, wid = tid >> 5, lane = tid & 31;
    const size_t tb = (size_t)bid * TS;
    const float* base = qkv + (size_t)(b * L + c * CH) * QC + h * DK;

    // ---- q: straight hi/lo split, warp per row, 8 rows/warp ----
#pragma unroll
    for (int it = 0; it < 8; ++it) {
        const int r = wid * 8 + it;
        const float2 v = *(const float2*)(base + (size_t)r * QC + lane * 2);
        __nv_bfloat16 h0, l0, h1, l1;
        split2(v.x, h0, l0); split2(v.y, h1, l1);
        *(__nv_bfloat162*)(qh + tb + r * 64 + lane * 2) = __nv_bfloat162(h0, h1);
        *(__nv_bfloat162*)(ql + tb + r * 64 + lane * 2) = __nv_bfloat162(l0, l1);
    }

    // ---- k: LN per row, write k hi/lo + stash normalized in smem ----
#pragma unroll
    for (int it = 0; it < 8; ++it) {
        const int r = wid * 8 + it;
        const float2 v = *(const float2*)(base + (size_t)r * QC + Dm + lane * 2);
        float s = v.x + v.y;
#pragma unroll
        for (int o = 16; o > 0; o >>= 1) s += __shfl_xor_sync(0xffffffffu, s, o);
        const float mu = s * (1.f / 64.f);
        const float d0 = v.x - mu, d1 = v.y - mu;
        float q2 = d0 * d0 + d1 * d1;
#pragma unroll
        for (int o = 16; o > 0; o >>= 1) q2 += __shfl_xor_sync(0xffffffffu, q2, o);
        const float rstd = rsqrtf(q2 * (1.f / 64.f) + 1e-5f);
        const float n0 = d0 * rstd, n1 = d1 * rstd;
        __nv_bfloat16 h0, l0, h1, l1;
        split2(n0, h0, l0); split2(n1, h1, l1);
        *(__nv_bfloat162*)(kh + tb + r * 64 + lane * 2) = __nv_bfloat162(h0, h1);
        *(__nv_bfloat162*)(kl + tb + r * 64 + lane * 2) = __nv_bfloat162(l0, l1);
        tile[r][lane * 2] = n0; tile[r][lane * 2 + 1] = n1;
    }
    __syncthreads();

    // ---- kT[e][t] from smem ----
#pragma unroll
    for (int it = 0; it < 8; ++it) {
        const int e = wid * 8 + it;
        const float x0 = tile[lane * 2][e], x1 = tile[lane * 2 + 1][e];
        __nv_bfloat16 h0, l0, h1, l1;
        split2(x0, h0, l0); split2(x1, h1, l1);
        *(__nv_bfloat162*)(kth + tb + e * 64 + lane * 2) = __nv_bfloat162(h0, h1);
        *(__nv_bfloat162*)(ktl + tb + e * 64 + lane * 2) = __nv_bfloat162(l0, l1);
    }
    __syncthreads();

    // ---- v into smem, then vT[d][t] ----
    for (int i = tid; i < TS; i += 256)
        tile[i >> 6][i & 63] = base[(size_t)(i >> 6) * QC + 2 * Dm + (i & 63)];
    __syncthreads();
#pragma unroll
    for (int it = 0; it < 8; ++it) {
        const int d = wid * 8 + it;
        const float x0 = tile[lane * 2][d], x1 = tile[lane * 2 + 1][d];
        __nv_bfloat16 h0, l0, h1, l1;
        split2(x0, h0, l0); split2(x1, h1, l1);
        *(__nv_bfloat162*)(vth + tb + d * 64 + lane * 2) = __nv_bfloat162(h0, h1);
        *(__nv_bfloat162*)(vtl + tb + d * 64 + lane * 2) = __nv_bfloat162(l0, l1);
    }
}

// ---------------------------------------------------------------------------
// chunk G: G[d][e] = sum_t v[t,d] k[t,e] = vT @ kT^T  (tensor, 3-pass)
// 128 threads (4 warps), per (b,h,c) block.
// ---------------------------------------------------------------------------
__global__ __launch_bounds__(128) void chunkG_kernel(
    const __nv_bfloat16* __restrict__ vth, const __nv_bfloat16* __restrict__ vtl,
    const __nv_bfloat16* __restrict__ kth, const __nv_bfloat16* __restrict__ ktl,
    float* __restrict__ G)
{
    using namespace cfg;
    __shared__ __align__(128) char sm[4 * 8192];
    const uint32_t sb = smem_u32(sm);
    const int bid = blockIdx.x, tid = threadIdx.x;
    const int wm = tid >> 5, lane = tid & 31;
    const size_t tb = (size_t)bid * TS;

    cp_tile_128(sb,          vth + tb, tid);
    cp_tile_128(sb + 8192,   vtl + tb, tid);
    cp_tile_128(sb + 16384,  kth + tb, tid);
    cp_tile_128(sb + 24576,  ktl + tb, tid);
    CP_COMMIT(); CP_WAIT(0);
    __syncthreads();

    float acc[8][4];
#pragma unroll
    for (int j = 0; j < 8; ++j)
#pragma unroll
        for (int r = 0; r < 4; ++r) acc[j][r] = 0.f;

    mma64_3pass(acc, sb, sb + 8192, sb + 16384, sb + 24576, wm, lane);

    const int qr = lane >> 2, qc = (lane & 3) * 2;
    float* Gp = G + tb;
#pragma unroll
    for (int j = 0; j < 8; ++j) {
        const int e = j * 8 + qc;
        *(float2*)(Gp + (wm * 16 + qr) * 64 + e)     = make_float2(acc[j][0], acc[j][1]);
        *(float2*)(Gp + (wm * 16 + qr + 8) * 64 + e) = make_float2(acc[j][2], acc[j][3]);
    }
}

// ---------------------------------------------------------------------------
// exclusive prefix over chunks + bf16 hi/lo split of S
// ---------------------------------------------------------------------------
__global__ __launch_bounds__(256) void prefix_split_kernel(
    const float* __restrict__ G, __nv_bfloat16* __restrict__ Sh,
    __nv_bfloat16* __restrict__ Sl)
{
    using namespace cfg;
    const int slice = blockIdx.x & 15, bh = blockIdx.x >> 4;
    const int idx = slice * 256 + threadIdx.x;
    const size_t base = (size_t)bh * NC * TS + idx;
    float run = 0.f;
    for (int c = 0; c < NC; ++c) {
        const size_t p = base + (size_t)c * TS;
        __nv_bfloat16 h, l; split2(run, h, l);
        Sh[p] = h; Sl[p] = l;
        run += G[p];
    }
}

// ---------------------------------------------------------------------------
// attention per chunk (tensor):
//   scores = tril(q @ k^T); out = q @ S^T + scores @ vT^T
//   writes y directly as bf16 hi/lo into token-major [T][Dm] buffers.
// 128 threads, 80 KiB dynamic smem.
// ---------------------------------------------------------------------------
__global__ __launch_bounds__(128) void attn_mma_kernel(
    const __nv_bfloat16* __restrict__ qh, const __nv_bfloat16* __restrict__ ql,
    const __nv_bfloat16* __restrict__ kh, const __nv_bfloat16* __restrict__ kl,
    const __nv_bfloat16* __restrict__ Sh, const __nv_bfloat16* __restrict__ Sl,
    const __nv_bfloat16* __restrict__ vth, const __nv_bfloat16* __restrict__ vtl,
    __nv_bfloat16* __restrict__ yh, __nv_bfloat16* __restrict__ yl)
{
    using namespace cfg;
    extern __shared__ __align__(128) char sm[];
    const uint32_t sb = smem_u32(sm);
    const uint32_t sQh = sb,           sQl = sb + 8192;
    const uint32_t sKh = sb + 16384,   sKl = sb + 24576;
    const uint32_t sSh = sb + 32768,   sSl = sb + 40960;
    const uint32_t sVh = sb + 49152,   sVl = sb + 57344;
    const uint32_t sCh = sb + 65536,   sCl = sb + 73728;

    const int bid = blockIdx.x, tid = threadIdx.x;
    const int wm = tid >> 5, lane = tid & 31;
    const int c = bid & 63, h = (bid >> 6) & 15, b = bid >> 10;
    const size_t tb = (size_t)bid * TS;

    cp_tile_128(sQh, qh + tb, tid);  cp_tile_128(sQl, ql + tb, tid);
    cp_tile_128(sKh, kh + tb, tid);  cp_tile_128(sKl, kl + tb, tid);
    cp_tile_128(sSh, Sh + tb, tid);  cp_tile_128(sSl, Sl + tb, tid);
    cp_tile_128(sVh, vth + tb, tid); cp_tile_128(sVl, vtl + tb, tid);
    CP_COMMIT(); CP_WAIT(0);
    __syncthreads();

    const int qr = lane >> 2, qc = (lane & 3) * 2;

    // ---- scores = q @ k^T, mask, store hi/lo to smem ----
    {
        float sc[8][4];
#pragma unroll
        for (int j = 0; j < 8; ++j)
#pragma unroll
            for (int r = 0; r < 4; ++r) sc[j][r] = 0.f;
        mma64_3pass(sc, sQh, sQl, sKh, sKl, wm, lane);

        const int t0 = wm * 16 + qr, t1 = t0 + 8;
#pragma unroll
        for (int j = 0; j < 8; ++j) {
            const int s0 = j * 8 + qc, s1 = s0 + 1;
            if (s0 > t0) sc[j][0] = 0.f;
            if (s1 > t0) sc[j][1] = 0.f;
            if (s0 > t1) sc[j][2] = 0.f;
            if (s1 > t1) sc[j][3] = 0.f;
            __nv_bfloat16 h0, l0, h1, l1, h2, l2, h3, l3;
            split2(sc[j][0], h0, l0); split2(sc[j][1], h1, l1);
            split2(sc[j][2], h2, l2); split2(sc[j][3], h3, l3);
            const uint32_t o0 = t0 * 128 + ((j ^ (t0 & 7)) * 16) + qc * 2;
            const uint32_t o1 = t1 * 128 + ((j ^ (t1 & 7)) * 16) + qc * 2;
            *(__nv_bfloat162*)(sm + (o0 - (sb - sb))) ; // no-op guard (kept simple below)
            *(__nv_bfloat162*)((char*)sm + (sCh - sb) + o0) = __nv_bfloat162(h0, h1);
            *(__nv_bfloat162*)((char*)sm + (sCl - sb) + o0) = __nv_bfloat162(l0, l1);
            *(__nv_bfloat162*)((char*)sm + (sCh - sb) + o1) = __nv_bfloat162(h2, h3);
            *(__nv_bfloat162*)((char*)sm + (sCl - sb) + o1) = __nv_bfloat162(l2, l3);
        }
    }
    __syncthreads();

    // ---- out = q @ S^T + scores @ vT^T ----
    float acc[8][4];
#pragma unroll
    for (int j = 0; j < 8; ++j)
#pragma unroll
        for (int r = 0; r < 4; ++r) acc[j][r] = 0.f;
    mma64_3pass(acc, sQh, sQl, sSh, sSl, wm, lane);
    mma64_3pass(acc, sCh, sCl, sVh, sVl, wm, lane);

    // ---- epilogue: bf16 hi/lo directly into [T][Dm] ----
    const int t0 = wm * 16 + qr;
    const size_t row0 = (size_t)(b * L + c * CH + t0) * Dm + h * DK;
    const size_t row1 = row0 + (size_t)8 * Dm;
#pragma unroll
    for (int j = 0; j < 8; ++j) {
        const int d = j * 8 + qc;
        __nv_bfloat16 h0, l0, h1, l1, h2, l2, h3, l3;
        split2(acc[j][0], h0, l0); split2(acc[j][1], h1, l1);
        split2(acc[j][2], h2, l2); split2(acc[j][3], h3, l3);
        *(__nv_bfloat162*)(yh + row0 + d) = __nv_bfloat162(h0, h1);
        *(__nv_bfloat162*)(yl + row0 + d) = __nv_bfloat162(l0, l1);
        *(__nv_bfloat162*)(yh + row1 + d) = __nv_bfloat162(h2, h3);
        *(__nv_bfloat162*)(yl + row1 + d) = __nv_bfloat162(l2, l3);
    }
}

// ---------------------------------------------------------------------------
// Launcher
// ---------------------------------------------------------------------------
extern "C" void kernel_launch(void* const* d_in, const int* in_sizes, int n_in,
                              void* d_out, int out_size)
{
    using namespace cfg;
    (void)in_sizes; (void)n_in; (void)out_size;
    const float* x    = (const float*)d_in[0];
    const float* Wqkv = (const float*)d_in[1];
    const float* Wo   = (const float*)d_in[2];
    float* out = (float*)d_out;

    float *qkv_p, *st_p;
    __nv_bfloat16 *ah, *al, *wqh, *wql, *woh, *wol;
    __nv_bfloat16 *pqh, *pql, *pkh, *pkl, *pkth, *pktl, *pvth, *pvtl, *psh, *psl;
    cudaGetSymbolAddress((void**)&qkv_p, g_qkv);
    cudaGetSymbolAddress((void**)&st_p,  g_state);
    cudaGetSymbolAddress((void**)&ah,  g_ahi);
    cudaGetSymbolAddress((void**)&al,  g_alo);
    cudaGetSymbolAddress((void**)&wqh, g_wqh);
    cudaGetSymbolAddress((void**)&wql, g_wql);
    cudaGetSymbolAddress((void**)&woh, g_woh);
    cudaGetSymbolAddress((void**)&wol, g_wol);
    cudaGetSymbolAddress((void**)&pqh, g_qh);
    cudaGetSymbolAddress((void**)&pql, g_ql);
    cudaGetSymbolAddress((void**)&pkh, g_kh);
    cudaGetSymbolAddress((void**)&pkl, g_kl);
    cudaGetSymbolAddress((void**)&pkth, g_kth);
    cudaGetSymbolAddress((void**)&pktl, g_ktl);
    cudaGetSymbolAddress((void**)&pvth, g_vth);
    cudaGetSymbolAddress((void**)&pvtl, g_vtl);
    cudaGetSymbolAddress((void**)&psh, g_sh);
    cudaGetSymbolAddress((void**)&psl, g_sl);

    static int attr_set = 0;
    if (!attr_set) {
        cudaFuncSetAttribute(gemm_mma_kernel,
                             cudaFuncAttributeMaxDynamicSharedMemorySize, gm::SMEM_SZ);
        cudaFuncSetAttribute(attn_mma_kernel,
                             cudaFuncAttributeMaxDynamicSharedMemorySize, 81920);
        attr_set = 1;
    }

    const int n4x = T * Dm / 4;
    split_kernel<<<(n4x + 255) / 256, 256>>>(x, ah, al, n4x);
    split_t_kernel<<<dim3(QC / 32, Dm / 32), 256>>>(Wqkv, wqh, wql, Dm, QC);
    split_t_kernel<<<dim3(Dm / 32, Dm / 32), 256>>>(Wo, woh, wol, Dm, Dm);

    gemm_mma_kernel<<<dim3(QC / 128, T / 128), 512, gm::SMEM_SZ>>>(
        ah, al, wqh, wql, qkv_p, QC, Dm);

    postproc_kernel<<<NT, 256>>>(qkv_p, pqh, pql, pkh, pkl, pkth, pktl, pvth, pvtl);
    chunkG_kernel<<<NT, 128>>>(pvth, pvtl, pkth, pktl, st_p);
    prefix_split_kernel<<<B * NH * 16, 256>>>(st_p, psh, psl);
    attn_mma_kernel<<<NT, 128, 81920>>>(pqh, pql, pkh, pkl, psh, psl,
                                        pvth, pvtl, ah, al);

    gemm_mma_kernel<<<dim3(Dm / 128, T / 128), 512, gm::SMEM_SZ>>>(
        ah, al, woh, wol, out, Dm, Dm);
}